// round 9
// baseline (speedup 1.0000x reference)
#include <cuda_runtime.h>

typedef unsigned long long ull;

#define C_ 64
#define D_ 32
#define S_ 32
#define HW_ 4096
#define DHW_ 131072

#define XROW 66                 /* x-tile row stride: [w][d][c] */
#define PIXST 2120              /* 32*66 + 8 */
#define OROW 35                 /* otile [c*4+w][d] */
#define OFF_R1 0
#define N_R1 8960               /* max(x-tile 4*2120=8480, otile 256*35=8960) */
#define OFF_SC N_R1             /* per-warp kT-then-vS buffer */
#define SCW 1152                /* kT: 32 rows x 36 ; vS: 16 rows x 68 (1088) */
#define OFF_WQ (OFF_SC + 4*SCW)          /* 13568: Wq [s][c] stride 68 */
#define OFF_WO (OFF_WQ + S_*68)          /* 15744: Wo [c][s] stride 36 */
#define SMEM_FLOATS (OFF_WO + C_*36)     /* 18048 floats = 72192 B */

__constant__ float cWK[S_*C_];
__constant__ float cWV[S_*C_];
__constant__ float cBK[S_];
__constant__ float cBQ[S_];
__constant__ float cBV[S_];
__constant__ float cBO[C_];

__device__ __forceinline__ ull f2fma(ull a, ull b, ull c) {
    ull d; asm("fma.rn.f32x2 %0,%1,%2,%3;" : "=l"(d) : "l"(a), "l"(b), "l"(c)); return d;
}
__device__ __forceinline__ ull f2add(ull a, ull b) {
    ull d; asm("add.rn.f32x2 %0,%1,%2;" : "=l"(d) : "l"(a), "l"(b)); return d;
}
__device__ __forceinline__ ull f2dup(float x) {
    ull d; asm("mov.b64 %0,{%1,%1};" : "=l"(d) : "f"(x)); return d;
}
__device__ __forceinline__ ull f2pack(float x, float y) {
    ull d; asm("mov.b64 %0,{%1,%2};" : "=l"(d) : "f"(x), "f"(y)); return d;
}
__device__ __forceinline__ float2 f2unpack(ull a) {
    float lo, hi; asm("mov.b64 {%0,%1},%2;" : "=f"(lo), "=f"(hi) : "l"(a));
    return make_float2(lo, hi);
}
__device__ __forceinline__ float hadd(ull a) {
    const float2 p = f2unpack(a); return p.x + p.y;
}

/* projection pass body: acc[s] (c-pair packed) over both x halves.
   WLOAD(s, hf, t) must yield a ulonglong2 of 4 consecutive c-weights of row s. */
#define PROJ_BODY(WLOAD, acc) {                                              \
    _Pragma("unroll")                                                        \
    for (int s = 0; s < 32; s++) acc[s] = 0ULL;                              \
    for (int hf = 0; hf < 2; hf++) {                                         \
        ull xh[16];                                                          \
        _Pragma("unroll")                                                    \
        for (int t = 0; t < 16; t++) xh[t] = *(const ull*)&xr[hf*32 + 2*t];  \
        _Pragma("unroll")                                                    \
        for (int s = 0; s < 32; s++) {                                       \
            ull a0 = acc[s], a1 = 0ULL;                                      \
            _Pragma("unroll")                                                \
            for (int t = 0; t < 8; t++) {                                    \
                const ulonglong2 w2 = WLOAD(s, hf, t);                       \
                a0 = f2fma(w2.x, xh[2*t],   a0);                             \
                a1 = f2fma(w2.y, xh[2*t+1], a1);                             \
            }                                                                \
            acc[s] = f2add(a0, a1);                                          \
        }                                                                    \
    }                                                                        \
}

#define WK_LOAD(s, hf, t) (*(const ulonglong2*)&cWK[(s)*64 + (hf)*32 + 4*(t)])
#define WV_LOAD(s, hf, t) (*(const ulonglong2*)&cWV[(s)*64 + (hf)*32 + 4*(t)])
#define WQ_LOAD(s, hf, t) (*(const ulonglong2*)&sm[OFF_WQ + (s)*68 + (hf)*32 + 4*(t)])

__global__ void __launch_bounds__(128, 3)
attn_fused_kernel(const float* __restrict__ x,
                  const float* __restrict__ Wq,
                  const float* __restrict__ Wo,
                  float* __restrict__ out)
{
    extern __shared__ float sm[];
    const int tid = threadIdx.x;
    const int bx  = blockIdx.x;
    const int wt  = bx & 15;
    const int h   = (bx >> 4) & 63;
    const int b   = bx >> 10;
    const int w0  = wt * 4;
    const int xbase = b*C_*DHW_ + h*64 + w0;

    /* ---- stage Wq [s][c] stride 68, Wo [c][s] stride 36 ---- */
    for (int i = tid; i < S_*C_; i += 128) {
        sm[OFF_WQ + (i >> 6)*68 + (i & 63)] = Wq[i];
        sm[OFF_WO + (i >> 5)*36 + (i & 31)] = Wo[i];
    }
    /* ---- stage x tile [w][d][c] ---- */
    for (int e = tid; e < C_*D_*4; e += 128) {
        const int w = e & 3;
        const int d = (e >> 2) & 31;
        const int c = e >> 7;
        sm[OFF_R1 + w*PIXST + d*XROW + c] = x[xbase + c*DHW_ + d*HW_ + w];
    }
    __syncthreads();

    const int warp = tid >> 5;      /* pixel */
    const int lane = tid & 31;      /* d (and j) */
    const float* xr = sm + OFF_R1 + warp*PIXST + lane*XROW;
    float* sc = sm + OFF_SC + warp*SCW;    /* kT then vS */

    /* ================= K pass (LDC) -> kT[i=lane][s] ================= */
    {
        ull acc[32];
        PROJ_BODY(WK_LOAD, acc);
#pragma unroll
        for (int g = 0; g < 8; g++) {
            ulonglong2 pr;
            pr.x = f2pack(hadd(acc[4*g  ]) + cBK[4*g  ],
                          hadd(acc[4*g+1]) + cBK[4*g+1]);
            pr.y = f2pack(hadd(acc[4*g+2]) + cBK[4*g+2],
                          hadd(acc[4*g+3]) + cBK[4*g+3]);
            *(ulonglong2*)&sc[lane*36 + 4*g] = pr;
        }
    }

    /* ================= Q pass (LDS) -> q2 s-pairs in regs ================= */
    ull q2[16];
    {
        ull acc[32];
        PROJ_BODY(WQ_LOAD, acc);
#pragma unroll
        for (int g = 0; g < 16; g++)
            q2[g] = f2pack(hadd(acc[2*g])   + cBQ[2*g],
                           hadd(acc[2*g+1]) + cBQ[2*g+1]);
    }
    __syncwarp();

    /* ======= scores a[i], this lane = column j ======= */
    float a[D_];
#pragma unroll
    for (int i = 0; i < D_; i++) {
        ull a0 = 0ULL, a1 = 0ULL;
#pragma unroll
        for (int t = 0; t < 8; t++) {
            const ulonglong2 kk = *(const ulonglong2*)&sc[i*36 + 4*t];
            a0 = f2fma(kk.x, q2[2*t],   a0);
            a1 = f2fma(kk.y, q2[2*t+1], a1);
        }
        a[i] = hadd(f2add(a0, a1)) * 0.17677669529663687f;  /* 1/sqrt(32) */
    }

    /* ======= softmax over i ======= */
    {
        float m = a[0];
#pragma unroll
        for (int i = 1; i < D_; i++) m = fmaxf(m, a[i]);
        float ssum = 0.f;
#pragma unroll
        for (int i = 0; i < D_; i++) { a[i] = __expf(a[i] - m); ssum += a[i]; }
        const float inv = 1.0f / ssum;
#pragma unroll
        for (int i = 0; i < D_; i++) a[i] *= inv;
    }
    __syncwarp();    /* kT reads done -> buffer may become vS */

    /* ================= V pass (LDC) -> vS[sp][2i] (overwrites kT) ========= */
    {
        ull acc[32];
        PROJ_BODY(WV_LOAD, acc);
#pragma unroll
        for (int sp = 0; sp < 16; sp++)
            *(ull*)&sc[sp*68 + 2*lane] =
                f2pack(hadd(acc[2*sp])   + cBV[2*sp],
                       hadd(acc[2*sp+1]) + cBV[2*sp+1]);
    }
    __syncwarp();

    /* ======= o2[sp] = sum_i vS(sp,i) * a[i]  (i-pair outer, dup on the fly) */
    ull o2[16];
#pragma unroll
    for (int sp = 0; sp < 16; sp++) o2[sp] = 0ULL;
#pragma unroll
    for (int t = 0; t < 16; t++) {
        const ull d0 = f2dup(a[2*t]);
        const ull d1 = f2dup(a[2*t+1]);
#pragma unroll
        for (int sp = 0; sp < 16; sp++) {
            const ulonglong2 vv = *(const ulonglong2*)&sc[sp*68 + 4*t];
            o2[sp] = f2fma(vv.x, d0, o2[sp]);
            o2[sp] = f2fma(vv.y, d1, o2[sp]);
        }
    }
    __syncthreads();   /* x-tile fully consumed (V pass done) -> otile overlay */

    /* ======= outproj (LDS Wo) -> otile[(c*4+warp)][lane] ======= */
#pragma unroll 4
    for (int c = 0; c < C_; c++) {
        ull a0 = 0ULL, a1 = 0ULL;
#pragma unroll
        for (int t = 0; t < 8; t++) {
            const ulonglong2 ww = *(const ulonglong2*)&sm[OFF_WO + c*36 + 4*t];
            a0 = f2fma(ww.x, o2[2*t],   a0);
            a1 = f2fma(ww.y, o2[2*t+1], a1);
        }
        sm[OFF_R1 + (c*4 + warp)*OROW + lane] = hadd(f2add(a0, a1)) + cBO[c];
    }
    __syncthreads();

    /* ======= final: out = otile + residual (x re-read, coalesced) ======= */
    for (int e = tid; e < C_*D_; e += 128) {
        const int d = e & 31;
        const int c = e >> 5;
        const float4 xv = *(const float4*)&x[xbase + c*DHW_ + d*HW_];
        float4 r;
        r.x = xv.x + sm[OFF_R1 + (c*4 + 0)*OROW + d];
        r.y = xv.y + sm[OFF_R1 + (c*4 + 1)*OROW + d];
        r.z = xv.z + sm[OFF_R1 + (c*4 + 2)*OROW + d];
        r.w = xv.w + sm[OFF_R1 + (c*4 + 3)*OROW + d];
        *(float4*)&out[xbase + c*DHW_ + d*HW_] = r;
    }
}

extern "C" void kernel_launch(void* const* d_in, const int* in_sizes, int n_in,
                              void* d_out, int out_size)
{
    const float* x  = (const float*)d_in[0];
    const float* Wq = (const float*)d_in[3];
    const float* Wo = (const float*)d_in[7];
    float* out = (float*)d_out;

    cudaMemcpyToSymbolAsync(cWK, d_in[1], S_*C_*sizeof(float), 0, cudaMemcpyDeviceToDevice, 0);
    cudaMemcpyToSymbolAsync(cBK, d_in[2], S_*sizeof(float),    0, cudaMemcpyDeviceToDevice, 0);
    cudaMemcpyToSymbolAsync(cBQ, d_in[4], S_*sizeof(float),    0, cudaMemcpyDeviceToDevice, 0);
    cudaMemcpyToSymbolAsync(cWV, d_in[5], S_*C_*sizeof(float), 0, cudaMemcpyDeviceToDevice, 0);
    cudaMemcpyToSymbolAsync(cBV, d_in[6], S_*sizeof(float),    0, cudaMemcpyDeviceToDevice, 0);
    cudaMemcpyToSymbolAsync(cBO, d_in[8], C_*sizeof(float),    0, cudaMemcpyDeviceToDevice, 0);

    const size_t smem_bytes = (size_t)SMEM_FLOATS * sizeof(float);
    cudaFuncSetAttribute(attn_fused_kernel,
                         cudaFuncAttributeMaxDynamicSharedMemorySize,
                         (int)smem_bytes);

    const int grid = 4 * 64 * 16;   /* B * H * (W/4) = 4096 */
    attn_fused_kernel<<<grid, 128, smem_bytes>>>(x, Wq, Wo, out);
}

// round 10
// speedup vs baseline: 1.3204x; 1.3204x over previous
#include <cuda_runtime.h>

typedef unsigned long long ull;

#define TW 4
#define C_ 64
#define D_ 32
#define S_ 32
#define SP_ 16
#define HW_ 4096
#define DHW_ 131072

#define XROW 68          /* x-tile: [w][d][c-contig] */
#define PIXST 2184       /* 32*68 + 8 */
#define OROW 35          /* otile [(c*4+w)][d] — overlays x-tile region */
#define OFF_R1 0
#define N_R1 8960        /* max(x 4*2184=8736, otile 256*35=8960) */
#define OFF_SC N_R1
#define SCW 1152         /* per-warp: kT 32x36=1152, then vS 16x68=1088 */
#define SMEM_FLOATS (OFF_SC + 4*SCW)   /* 13568 floats = 54272 B */

__constant__ float cWK[S_*C_];
__constant__ float cWQ[S_*C_];
__constant__ float cWV[S_*C_];
__constant__ float cWO[C_*S_];
__constant__ float cBK[S_];
__constant__ float cBQ[S_];
__constant__ float cBV[S_];
__constant__ float cBO[C_];

__device__ __forceinline__ ull f2fma(ull a, ull b, ull c) {
    ull d; asm("fma.rn.f32x2 %0,%1,%2,%3;" : "=l"(d) : "l"(a), "l"(b), "l"(c)); return d;
}
__device__ __forceinline__ ull f2add(ull a, ull b) {
    ull d; asm("add.rn.f32x2 %0,%1,%2;" : "=l"(d) : "l"(a), "l"(b)); return d;
}
__device__ __forceinline__ ull f2dup(float x) {
    ull d; asm("mov.b64 %0,{%1,%1};" : "=l"(d) : "f"(x)); return d;
}
__device__ __forceinline__ ull f2pack(float x, float y) {
    ull d; asm("mov.b64 %0,{%1,%2};" : "=l"(d) : "f"(x), "f"(y)); return d;
}
__device__ __forceinline__ float2 f2unpack(ull a) {
    float lo, hi; asm("mov.b64 {%0,%1},%2;" : "=f"(lo), "=f"(hi) : "l"(a));
    return make_float2(lo, hi);
}

/* one projection output channel s: dot(W[s,:], x) + b[s], c-pair packed.
   Round-3 structure: 4 short accumulator chains, x register-resident. */
#define PROJ_S(CW, CB, sIdx, val) {                                          \
    ull pa0=0ULL, pa1=0ULL, pa2=0ULL, pa3=0ULL;                              \
    _Pragma("unroll")                                                        \
    for (int t = 0; t < 16; t += 2) {                                        \
        const ulonglong2 wA = *(const ulonglong2*)&CW[(sIdx)*C_ + 4*t];      \
        pa0 = f2fma(wA.x, x2[2*t],   pa0);                                   \
        pa1 = f2fma(wA.y, x2[2*t+1], pa1);                                   \
        const ulonglong2 wB = *(const ulonglong2*)&CW[(sIdx)*C_ + 4*t + 4];  \
        pa2 = f2fma(wB.x, x2[2*t+2], pa2);                                   \
        pa3 = f2fma(wB.y, x2[2*t+3], pa3);                                   \
    }                                                                        \
    const float2 pp = f2unpack(f2add(f2add(pa0,pa2), f2add(pa1,pa3)));       \
    val = pp.x + pp.y + CB[sIdx];                                            \
}

__global__ void __launch_bounds__(128, 4)
attn_fused_kernel(const float* __restrict__ x, float* __restrict__ out)
{
    extern __shared__ float sm[];
    const int tid = threadIdx.x;
    const int bx  = blockIdx.x;
    const int wt  = bx & 15;
    const int h   = (bx >> 4) & 63;
    const int b   = bx >> 10;
    const int w0  = wt * TW;
    const int xbase = b*C_*DHW_ + h*64 + w0;

    /* ---- stage x tile: [w][d][c-contig] ---- */
    for (int e = tid; e < C_*D_*TW; e += 128) {
        const int w = e & 3;
        const int d = (e >> 2) & 31;
        const int c = e >> 7;
        sm[OFF_R1 + w*PIXST + d*XROW + c] = x[xbase + c*DHW_ + d*HW_ + w];
    }
    __syncthreads();

    const int warp = tid >> 5;    /* pixel */
    const int lane = tid & 31;    /* d (and j) */

    /* ---- x fully into registers (16 LDS.128, conflict-free) ---- */
    ull x2[32];
    {
        const float* xr = sm + OFF_R1 + warp*PIXST + lane*XROW;
#pragma unroll
        for (int t = 0; t < 16; t++) {
            const ulonglong2 v = *(const ulonglong2*)&xr[4*t];
            x2[2*t] = v.x; x2[2*t+1] = v.y;
        }
    }

    float* sc = sm + OFF_SC + warp*SCW;   /* kT then vS */

    /* ---- K pass -> kT[i=lane][s] (stride 36) ---- */
#pragma unroll 4
    for (int sp = 0; sp < SP_; sp++) {
        float v0, v1;
        PROJ_S(cWK, cBK, 2*sp,   v0);
        PROJ_S(cWK, cBK, 2*sp+1, v1);
        *(ull*)&sc[lane*36 + 2*sp] = f2pack(v0, v1);
    }

    /* ---- Q pass (kept in registers as s-pairs) ---- */
    ull q2[SP_];
#pragma unroll
    for (int sp = 0; sp < SP_; sp++) {
        float v0, v1;
        PROJ_S(cWQ, cBQ, 2*sp,   v0);
        PROJ_S(cWQ, cBQ, 2*sp+1, v1);
        q2[sp] = f2pack(v0, v1);
    }
    __syncwarp();

    /* ---- scores[i][j=lane] ---- */
    float a[D_];
#pragma unroll
    for (int i = 0; i < D_; i++) {
        ull a0 = 0ULL, a1 = 0ULL;
#pragma unroll
        for (int t = 0; t < 8; t++) {
            const ulonglong2 kk = *(const ulonglong2*)&sc[i*36 + 4*t];
            a0 = f2fma(kk.x, q2[2*t],   a0);
            a1 = f2fma(kk.y, q2[2*t+1], a1);
        }
        const float2 p = f2unpack(f2add(a0, a1));
        a[i] = (p.x + p.y) * 0.17677669529663687f;   /* 1/sqrt(32) */
    }

    /* ---- softmax over i ---- */
    {
        float m = a[0];
#pragma unroll
        for (int i = 1; i < D_; i++) m = fmaxf(m, a[i]);
        float ssum = 0.f;
#pragma unroll
        for (int i = 0; i < D_; i++) { a[i] = __expf(a[i] - m); ssum += a[i]; }
        const float inv = 1.0f / ssum;
#pragma unroll
        for (int i = 0; i < D_; i++) a[i] *= inv;
    }
    __syncwarp();   /* kT reads complete -> buffer becomes vS */

    /* ---- V pass -> vS[sp][2i] (stride 68), overwrites kT ---- */
#pragma unroll 4
    for (int sp = 0; sp < SP_; sp++) {
        float v0, v1;
        PROJ_S(cWV, cBV, 2*sp,   v0);
        PROJ_S(cWV, cBV, 2*sp+1, v1);
        *(ull*)&sc[sp*68 + 2*lane] = f2pack(v0, v1);
    }
    __syncwarp();

    /* ---- o2[sp] = sum_i vS(sp,i) * a[i] (dup a on the fly) ---- */
    ull o2[SP_];
#pragma unroll
    for (int sp = 0; sp < SP_; sp++) o2[sp] = 0ULL;
#pragma unroll
    for (int t = 0; t < 16; t++) {
        const ull d0 = f2dup(a[2*t]);
        const ull d1 = f2dup(a[2*t+1]);
#pragma unroll
        for (int sp = 0; sp < SP_; sp++) {
            const ulonglong2 vv = *(const ulonglong2*)&sc[sp*68 + 4*t];
            o2[sp] = f2fma(vv.x, d0, o2[sp]);
            o2[sp] = f2fma(vv.y, d1, o2[sp]);
        }
    }
    __syncthreads();   /* x-tile fully consumed -> otile overlay */

    /* ---- outproj -> otile[(c*4+warp)][lane] ---- */
#pragma unroll 8
    for (int c = 0; c < C_; c++) {
        ull a0 = 0ULL, a1 = 0ULL;
#pragma unroll
        for (int t = 0; t < 8; t++) {
            const ulonglong2 ww = *(const ulonglong2*)&cWO[c*S_ + 4*t];
            a0 = f2fma(ww.x, o2[2*t],   a0);
            a1 = f2fma(ww.y, o2[2*t+1], a1);
        }
        const float2 p = f2unpack(f2add(a0, a1));
        sm[OFF_R1 + (c*TW + warp)*OROW + lane] = p.x + p.y + cBO[c];
    }
    __syncthreads();

    /* ---- final: out = otile + residual (x re-read from global) ---- */
    for (int e = tid; e < C_*D_; e += 128) {
        const int d = e & 31;
        const int c = e >> 5;
        const float4 xv = *(const float4*)&x[xbase + c*DHW_ + d*HW_];
        float4 r;
        r.x = xv.x + sm[OFF_R1 + (c*TW + 0)*OROW + d];
        r.y = xv.y + sm[OFF_R1 + (c*TW + 1)*OROW + d];
        r.z = xv.z + sm[OFF_R1 + (c*TW + 2)*OROW + d];
        r.w = xv.w + sm[OFF_R1 + (c*TW + 3)*OROW + d];
        *(float4*)&out[xbase + c*DHW_ + d*HW_] = r;
    }
}

extern "C" void kernel_launch(void* const* d_in, const int* in_sizes, int n_in,
                              void* d_out, int out_size)
{
    const float* x = (const float*)d_in[0];
    float* out = (float*)d_out;

    cudaMemcpyToSymbolAsync(cWK, d_in[1], S_*C_*sizeof(float), 0, cudaMemcpyDeviceToDevice, 0);
    cudaMemcpyToSymbolAsync(cBK, d_in[2], S_*sizeof(float),    0, cudaMemcpyDeviceToDevice, 0);
    cudaMemcpyToSymbolAsync(cWQ, d_in[3], S_*C_*sizeof(float), 0, cudaMemcpyDeviceToDevice, 0);
    cudaMemcpyToSymbolAsync(cBQ, d_in[4], S_*sizeof(float),    0, cudaMemcpyDeviceToDevice, 0);
    cudaMemcpyToSymbolAsync(cWV, d_in[5], S_*C_*sizeof(float), 0, cudaMemcpyDeviceToDevice, 0);
    cudaMemcpyToSymbolAsync(cBV, d_in[6], S_*sizeof(float),    0, cudaMemcpyDeviceToDevice, 0);
    cudaMemcpyToSymbolAsync(cWO, d_in[7], C_*S_*sizeof(float), 0, cudaMemcpyDeviceToDevice, 0);
    cudaMemcpyToSymbolAsync(cBO, d_in[8], C_*sizeof(float),    0, cudaMemcpyDeviceToDevice, 0);

    const size_t smem_bytes = (size_t)SMEM_FLOATS * sizeof(float);
    cudaFuncSetAttribute(attn_fused_kernel,
                         cudaFuncAttributeMaxDynamicSharedMemorySize,
                         (int)smem_bytes);

    const int grid = 4 * 64 * 16;   /* B * H * (W/TW) = 4096 */
    attn_fused_kernel<<<grid, 128, smem_bytes>>>(x, out);
}